// round 8
// baseline (speedup 1.0000x reference)
#include <cuda_runtime.h>
#include <cstdint>

// LSTM decoder, persistent per-CTA recurrence. 512 threads.
// Thread = (unit u in [0,128), k-group kg in {0..3} of 32 k's).
// Each thread: the 4 gate rows of one unit (quad weight float4) over its 32 k's,
// all 7 batch-pairs; plus one Wo row on a bp-half. k-partials reduced by
// intra-warp shuffles (lane = kg*8 + unit-low-3-bits). c register-resident.
// B=2048, L=64, H=128, 4H=512, O=64, T=512, fp32.
// Identity: x_t == h_t for t>=1 => gates = h @ (W_ih+W_hh)^T + (b_ih+b_hh).
// t==0: x=0 => gates = h0 @ W_hh^T + (b_ih+b_hh).

typedef unsigned long long ull;

#define Lq   64
#define Hq   128
#define Oq   64
#define Tq   512
#define NPB  7      // batch pairs per CTA (14 slots)
#define HS   20     // h_s row stride in floats (80 B)

// Quad-packed weights: g_Wq[k*128 + u] = (W[u][k], W[u+128][k], W[u+256][k], W[u+384][k])
__device__ float4 g_Wq [Hq * Hq];   // combined W_ih + W_hh
__device__ float4 g_Whq[Hq * Hq];   // W_hh only (step 0)

// ---------- helpers ----------
__device__ __forceinline__ ull fma2(ull a, ull b, ull c) {
    ull d; asm("fma.rn.f32x2 %0, %1, %2, %3;" : "=l"(d) : "l"(a), "l"(b), "l"(c)); return d;
}
__device__ __forceinline__ ull add2(ull a, ull b) {
    ull d; asm("add.rn.f32x2 %0, %1, %2;" : "=l"(d) : "l"(a), "l"(b)); return d;
}
__device__ __forceinline__ ull dup2(float x) {
    ull d; asm("mov.b64 %0, {%1, %1};" : "=l"(d) : "f"(x)); return d;
}
__device__ __forceinline__ ull pack2(float lo, float hi) {
    ull d; asm("mov.b64 %0, {%1, %2};" : "=l"(d) : "f"(lo), "f"(hi)); return d;
}
__device__ __forceinline__ void unpk(ull a, float& lo, float& hi) {
    asm("mov.b64 {%0, %1}, %2;" : "=f"(lo), "=f"(hi) : "l"(a));
}
__device__ __forceinline__ void ldsv2(ull& a, ull& b, unsigned addr) {
    asm volatile("ld.shared.v2.u64 {%0, %1}, [%2];" : "=l"(a), "=l"(b) : "r"(addr));
}
__device__ __forceinline__ ull lds64(unsigned addr) {
    ull a; asm volatile("ld.shared.u64 %0, [%1];" : "=l"(a) : "r"(addr)); return a;
}
__device__ __forceinline__ void sts64(unsigned addr, ull v) {
    asm volatile("st.shared.u64 [%0], %1;" :: "r"(addr), "l"(v));
}
__device__ __forceinline__ void sts32(unsigned addr, float v) {
    asm volatile("st.shared.f32 [%0], %1;" :: "r"(addr), "f"(v));
}
__device__ __forceinline__ unsigned sm_u32(const void* p) {
    unsigned r;
    asm("{ .reg .u64 t; cvta.to.shared.u64 t, %1; cvt.u32.u64 %0, t; }" : "=r"(r) : "l"(p));
    return r;
}
__device__ __forceinline__ ull shflx64(ull v, int m) {
    return __shfl_xor_sync(0xffffffffu, v, m);
}
__device__ __forceinline__ float sigf(float x)   { return __fdividef(1.f, 1.f + __expf(-x)); }
__device__ __forceinline__ float tanhf2(float x) { return __fdividef(2.f, 1.f + __expf(-2.f * x)) - 1.f; }

// ---------- prep: quad-pack transposed weights ----------
__global__ void decoder_prep(const float* __restrict__ Wih, const float* __restrict__ Whh) {
    int i = blockIdx.x * blockDim.x + threadIdx.x;   // i = k*128 + u
    if (i < Hq * Hq) {
        int u = i & 127, k = i >> 7;
        float4 wh, wc;
        wh.x = Whh[u * Hq + k];          wc.x = Wih[u * Hq + k]          + wh.x;
        wh.y = Whh[(u + 128) * Hq + k];  wc.y = Wih[(u + 128) * Hq + k]  + wh.y;
        wh.z = Whh[(u + 256) * Hq + k];  wc.z = Wih[(u + 256) * Hq + k]  + wh.z;
        wh.w = Whh[(u + 384) * Hq + k];  wc.w = Wih[(u + 384) * Hq + k]  + wh.w;
        g_Wq[i] = wc;  g_Whq[i] = wh;
    }
}

// ---------- fused GEMM: 4 gate rows (+1 out row on a bp-half) over 32 k's ----------
// OSEL 0: out bp 0..3 (warps 0-7); OSEL 1: out bp 4..6 (warps 8-15).
template <int OSEL>
__device__ __forceinline__ void gemm32(
    const float4* __restrict__ wq,    // global quad weights, pre-offset (kg*32*128 + u)
    const float*  __restrict__ wo_sp, // SMEM Wo_s + kg*32*64 + o-row
    unsigned hbk,                     // h_s byte addr + kg*32*80
    ull (&A)[4][7], ull (&Aw)[4])
{
#pragma unroll 4
    for (int i = 0; i < 32; i++) {
        float4 w = __ldg(wq + i * 128);
        float  wo = wo_sp[i * 64];
        unsigned a = hbk + (unsigned)(i * (HS * 4));
        ull h0, h1, h2, h3, h4, h5, h6;
        ldsv2(h0, h1, a);
        ldsv2(h2, h3, a + 16);
        ldsv2(h4, h5, a + 32);
        h6 = lds64(a + 48);
        ull hh[7] = {h0, h1, h2, h3, h4, h5, h6};
        ull wi = dup2(w.x), wf = dup2(w.y), wg = dup2(w.z), wo4 = dup2(w.w);
        ull wwo = dup2(wo);
#pragma unroll
        for (int bp = 0; bp < NPB; bp++) {
            A[0][bp] = fma2(wi,  hh[bp], A[0][bp]);
            A[1][bp] = fma2(wf,  hh[bp], A[1][bp]);
            A[2][bp] = fma2(wg,  hh[bp], A[2][bp]);
            A[3][bp] = fma2(wo4, hh[bp], A[3][bp]);
        }
        if (OSEL == 0) {
#pragma unroll
            for (int j = 0; j < 4; j++) Aw[j] = fma2(wwo, hh[j], Aw[j]);
        } else {
#pragma unroll
            for (int j = 0; j < 3; j++) Aw[j] = fma2(wwo, hh[4 + j], Aw[j]);
        }
    }
}

// SMEM layout (float offsets):
//   Wo_s [128k][64o] @ 0     (8192)  Wo transposed
//   h_s  [128][20]   @ 8192  (2560)  h transposed [k][slot]
//   ob   [64o][15]   @ 10752 ( 960)  out staging (stride 15 -> conflict-free reads)
#define OFF_H   8192
#define OFF_OB  10752
#define SMEM_FLOATS 11712
#define SMEM_BYTES  (SMEM_FLOATS * 4)

__global__ void __launch_bounds__(512, 1) decoder_main(
    const float* __restrict__ latent, const float* __restrict__ fc_w, const float* __restrict__ fc_b,
    const float* __restrict__ b_ih,   const float* __restrict__ b_hh,
    const float* __restrict__ Wo,     const float* __restrict__ bo,
    float* __restrict__ out)
{
    extern __shared__ float sm[];
    float* Wo_s = sm;
    float* h_s  = sm + OFF_H;
    float* ob   = sm + OFF_OB;

    const int tid  = threadIdx.x;
    const int lane = tid & 31;
    const int warp = tid >> 5;          // 0..15
    const int kg   = lane >> 3;         // k-group 0..3
    const int kgb0 = kg & 1;
    const int kgb1 = kg >> 1;
    const int u    = warp * 8 + (lane & 7);   // unit 0..127
    const int osel = warp >> 3;               // 0: out bp0-3 row u; 1: out bp4-6 row u-64
    const int orow = osel ? (u - 64) : u;     // Wo row 0..63
    const int cta  = blockIdx.x;
    int bstart, nb;
    if (cta < 124) { bstart = cta * 14;                nb = 14; }
    else           { bstart = 1736 + (cta - 124) * 13; nb = 13; }

    // Wo transposed into SMEM: Wo_s[k*64+o] = Wo[o*128+k].
    for (int i = tid; i < Hq * Oq; i += 512) {
        int k = i >> 6, o = i & 63;
        Wo_s[i] = Wo[o * Hq + k];
    }
    for (int i = tid; i < Hq * HS; i += 512) h_s[i] = 0.f;
    __syncthreads();

    // h0 = latent @ fc_w^T + fc_b  (pad slots stay 0)
    for (int i = tid; i < 14 * Hq; i += 512) {
        int slot = i >> 7, hk = i & 127;
        float acc = 0.f;
        if (slot < nb) {
            acc = fc_b[hk];
            const float* lp = latent + (size_t)(bstart + slot) * Lq;
            const float* wp = fc_w + hk * Lq;
#pragma unroll 8
            for (int l = 0; l < Lq; l++) acc += lp[l] * wp[l];
        }
        h_s[hk * HS + slot] = acc;
    }

    // Biases: only kg==0 lanes inject them (summed once by the kg-reduction).
    ull bb[4];
#pragma unroll
    for (int g = 0; g < 4; g++) {
        float v = b_ih[g * 128 + u] + b_hh[g * 128 + u];
        bb[g] = (kg == 0) ? dup2(v) : 0ull;
    }
    const ull bow = (kg == 0) ? dup2(bo[orow]) : 0ull;

    // Register-resident cell state: this lane owns (u, bp) for its post-reduction bps.
    // Owner map after reduce-scatter: bp0,1->kg0; bp2,3->kg1; bp4,5->kg2; bp6->kg3.
    ull cR[2] = {0ull, 0ull};

    const unsigned hb  = sm_u32(h_s);
    const unsigned obb = sm_u32(ob);
    const unsigned hbk = hb + (unsigned)(kg * 32 * (HS * 4));
    const float4* pWc = g_Wq  + kg * 32 * Hq + u;
    const float4* pWh = g_Whq + kg * 32 * Hq + u;
    const float*  wo_sp = Wo_s + kg * 32 * Oq + orow;
    __syncthreads();

    for (int t = 0; t < Tq; t++) {
        // ---- phase 1: fused gate+out GEMM over this lane's 32 k's ----
        ull A[4][7], Aw[4];
#pragma unroll
        for (int g = 0; g < 4; g++)
#pragma unroll
            for (int bp = 0; bp < NPB; bp++) A[g][bp] = bb[g];
#pragma unroll
        for (int j = 0; j < 4; j++) Aw[j] = bow;

        const float4* wq = (t == 0) ? pWh : pWc;
        if (osel == 0) gemm32<0>(wq, wo_sp, hbk, A, Aw);
        else           gemm32<1>(wq, wo_sp, hbk, A, Aw);

        // ---- gate reduce-scatter over k-groups ----
        // Stage A (xor 16): kgb1=0 keeps bp0-3, kgb1=1 keeps bp4-6.
#pragma unroll
        for (int g = 0; g < 4; g++)
#pragma unroll
            for (int j = 0; j < 4; j++) {
                ull snd = kgb1 ? A[g][j] : ((j < 3) ? A[g][4 + j] : A[g][0]);
                ull rcv = shflx64(snd, 16);
                if (!kgb1)      A[g][j]     = add2(A[g][j],     rcv);
                else if (j < 3) A[g][4 + j] = add2(A[g][4 + j], rcv);
            }
        // Stage B (xor 8): kg0 keeps bp0,1; kg1 bp2,3; kg2 bp4,5; kg3 bp6.
#pragma unroll
        for (int g = 0; g < 4; g++)
#pragma unroll
            for (int j = 0; j < 2; j++) {
                ull snd;
                if (!kgb1) snd = kgb0 ? A[g][j] : A[g][2 + j];
                else       snd = kgb0 ? A[g][4 + j] : ((j == 0) ? A[g][6] : A[g][0]);
                ull rcv = shflx64(snd, 8);
                if (!kgb1) {
                    if (!kgb0) A[g][j]     = add2(A[g][j],     rcv);
                    else       A[g][2 + j] = add2(A[g][2 + j], rcv);
                } else {
                    if (!kgb0)          A[g][4 + j] = add2(A[g][4 + j], rcv);
                    else if (j == 0)    A[g][6]     = add2(A[g][6],     rcv);
                }
            }
        // Out-row full butterfly (sums the 4 kg copies; lanes keep same o-row).
#pragma unroll
        for (int j = 0; j < 4; j++) Aw[j] = add2(Aw[j], shflx64(Aw[j], 16));
#pragma unroll
        for (int j = 0; j < 4; j++) Aw[j] = add2(Aw[j], shflx64(Aw[j], 8));

        __syncthreads();   // all h_s reads of this step done

        // ---- phase 2: elementwise cell update in registers; write h to SMEM ----
#pragma unroll
        for (int bp = 0; bp < NPB; bp++) {
            int owner = (bp == 6) ? 3 : (bp >> 1);
            if (kg == owner) {
                int j = bp & 1;
                float gi0, gi1, gf0, gf1, gg0, gg1, go0, go1, cc0, cc1;
                unpk(A[0][bp], gi0, gi1);
                unpk(A[1][bp], gf0, gf1);
                unpk(A[2][bp], gg0, gg1);
                unpk(A[3][bp], go0, go1);
                unpk(cR[j], cc0, cc1);
                float nc0 = sigf(gf0) * cc0 + sigf(gi0) * tanhf2(gg0);
                float nc1 = sigf(gf1) * cc1 + sigf(gi1) * tanhf2(gg1);
                float hv0 = sigf(go0) * tanhf2(nc0);
                float hv1 = sigf(go1) * tanhf2(nc1);
                cR[j] = pack2(nc0, nc1);
                sts64(hb + (unsigned)(u * (HS * 4) + bp * 8), pack2(hv0, hv1));
            }
        }

        // ---- stage out[t-1]: kg==0 lanes write full sums to ob[o][15] ----
        if (kg == 0) {
            unsigned ow = obb + (unsigned)(orow * 60);   // 15 floats * 4 B
#pragma unroll
            for (int j = 0; j < 4; j++) {
                if (osel == 0 || j < 3) {
                    int s0 = osel ? (8 + 2 * j) : (2 * j);
                    float lo, hi;
                    unpk(Aw[j], lo, hi);
                    sts32(ow + (unsigned)(s0 * 4),     lo);
                    sts32(ow + (unsigned)(s0 * 4 + 4), hi);
                }
            }
        }
        __syncthreads();

        // ---- coalesced store of out[t-1]: warps 0-6, warp w -> slots 2w, 2w+1 ----
        if (t > 0 && warp < 7) {
#pragma unroll
            for (int si = 0; si < 2; si++) {
                int s = 2 * warp + si;
                if (s < nb) {
                    float v0 = ob[lane * 15 + s];
                    float v1 = ob[(lane + 32) * 15 + s];
                    size_t base = ((size_t)(bstart + s) * Tq + (t - 1)) * Oq;
                    out[base + lane]      = v0;
                    out[base + lane + 32] = v1;
                }
            }
        }
    }

    // ---- tail: out[T-1] from final h ----
    {
        ull Aw[4];
#pragma unroll
        for (int j = 0; j < 4; j++) Aw[j] = bow;
#pragma unroll 4
        for (int i = 0; i < 32; i++) {
            float wo = wo_sp[i * 64];
            ull wwo = dup2(wo);
            unsigned a = hbk + (unsigned)(i * (HS * 4));
            ull h0, h1, h2, h3, h4, h5, h6;
            ldsv2(h0, h1, a);
            ldsv2(h2, h3, a + 16);
            ldsv2(h4, h5, a + 32);
            h6 = lds64(a + 48);
            ull hh[7] = {h0, h1, h2, h3, h4, h5, h6};
            if (osel == 0) {
#pragma unroll
                for (int j = 0; j < 4; j++) Aw[j] = fma2(wwo, hh[j], Aw[j]);
            } else {
#pragma unroll
                for (int j = 0; j < 3; j++) Aw[j] = fma2(wwo, hh[4 + j], Aw[j]);
            }
        }
#pragma unroll
        for (int j = 0; j < 4; j++) Aw[j] = add2(Aw[j], shflx64(Aw[j], 16));
#pragma unroll
        for (int j = 0; j < 4; j++) Aw[j] = add2(Aw[j], shflx64(Aw[j], 8));

        __syncthreads();   // out[T-2] readers done with ob before overwrite

        if (kg == 0) {
            unsigned ow = obb + (unsigned)(orow * 60);
#pragma unroll
            for (int j = 0; j < 4; j++) {
                if (osel == 0 || j < 3) {
                    int s0 = osel ? (8 + 2 * j) : (2 * j);
                    float lo, hi;
                    unpk(Aw[j], lo, hi);
                    sts32(ow + (unsigned)(s0 * 4),     lo);
                    sts32(ow + (unsigned)(s0 * 4 + 4), hi);
                }
            }
        }
        __syncthreads();
        if (warp < 7) {
#pragma unroll
            for (int si = 0; si < 2; si++) {
                int s = 2 * warp + si;
                if (s < nb) {
                    float v0 = ob[lane * 15 + s];
                    float v1 = ob[(lane + 32) * 15 + s];
                    size_t base = ((size_t)(bstart + s) * Tq + (Tq - 1)) * Oq;
                    out[base + lane]      = v0;
                    out[base + lane + 32] = v1;
                }
            }
        }
    }
}

extern "C" void kernel_launch(void* const* d_in, const int* in_sizes, int n_in,
                              void* d_out, int out_size) {
    const float* latent = (const float*)d_in[0];
    const float* fc_w   = (const float*)d_in[1];
    const float* fc_b   = (const float*)d_in[2];
    const float* W_ih   = (const float*)d_in[3];
    const float* W_hh   = (const float*)d_in[4];
    const float* b_ih   = (const float*)d_in[5];
    const float* b_hh   = (const float*)d_in[6];
    const float* Wo     = (const float*)d_in[7];
    const float* bo     = (const float*)d_in[8];
    float* out = (float*)d_out;

    cudaFuncSetAttribute(decoder_main,
                         cudaFuncAttributeMaxDynamicSharedMemorySize, SMEM_BYTES);

    decoder_prep<<<(Hq * Hq + 511) / 512, 512>>>(W_ih, W_hh);
    decoder_main<<<148, 512, SMEM_BYTES>>>(latent, fc_w, fc_b, b_ih, b_hh, Wo, bo, out);
}

// round 9
// speedup vs baseline: 1.1873x; 1.1873x over previous
#include <cuda_runtime.h>
#include <cstdint>

// LSTM decoder, persistent per-CTA recurrence. 512 threads, G=8 rows/thread.
// warp w (0..15): units u0=(w&7)*8+ulow, u1=u0+64; bp-half bph=w>>3
//   (bph0: batch-pairs 0..3, bph1: 4..6). lane: kg=lane>>3 (32 k's each).
// Quad-0 weights in SMEM, quad-1 streamed LDG. kg-partials reduced by warp
// shuffles; each lane ends with complete (i,f,g,o) quads -> c in registers.
// B=2048, L=64, H=128, 4H=512, O=64, T=512, fp32.
// Identity: x_t == h_t for t>=1 => gates = h @ (W_ih+W_hh)^T + (b_ih+b_hh).
// t==0: x=0 => gates = h0 @ W_hh^T + (b_ih+b_hh).

typedef unsigned long long ull;

#define Lq   64
#define Hq   128
#define Oq   64
#define Tq   512
#define HS   20     // h_s row stride in floats (80 B)

// Quad-packed weights: g_Wq[k*128 + u] = (W[u][k], W[u+128][k], W[u+256][k], W[u+384][k])
__device__ float4 g_Wq [Hq * Hq];   // combined W_ih + W_hh
__device__ float4 g_Whq[Hq * Hq];   // W_hh only (step 0)

// ---------- helpers ----------
__device__ __forceinline__ ull fma2(ull a, ull b, ull c) {
    ull d; asm("fma.rn.f32x2 %0, %1, %2, %3;" : "=l"(d) : "l"(a), "l"(b), "l"(c)); return d;
}
__device__ __forceinline__ ull add2(ull a, ull b) {
    ull d; asm("add.rn.f32x2 %0, %1, %2;" : "=l"(d) : "l"(a), "l"(b)); return d;
}
__device__ __forceinline__ ull dup2(float x) {
    ull d; asm("mov.b64 %0, {%1, %1};" : "=l"(d) : "f"(x)); return d;
}
__device__ __forceinline__ ull pack2(float lo, float hi) {
    ull d; asm("mov.b64 %0, {%1, %2};" : "=l"(d) : "f"(lo), "f"(hi)); return d;
}
__device__ __forceinline__ void unpk(ull a, float& lo, float& hi) {
    asm("mov.b64 {%0, %1}, %2;" : "=f"(lo), "=f"(hi) : "l"(a));
}
__device__ __forceinline__ void ldsv2(ull& a, ull& b, unsigned addr) {
    asm volatile("ld.shared.v2.u64 {%0, %1}, [%2];" : "=l"(a), "=l"(b) : "r"(addr));
}
__device__ __forceinline__ ull lds64(unsigned addr) {
    ull a; asm volatile("ld.shared.u64 %0, [%1];" : "=l"(a) : "r"(addr)); return a;
}
__device__ __forceinline__ void sts64(unsigned addr, ull v) {
    asm volatile("st.shared.u64 [%0], %1;" :: "r"(addr), "l"(v));
}
__device__ __forceinline__ void sts32(unsigned addr, float v) {
    asm volatile("st.shared.f32 [%0], %1;" :: "r"(addr), "f"(v));
}
__device__ __forceinline__ unsigned sm_u32(const void* p) {
    unsigned r;
    asm("{ .reg .u64 t; cvta.to.shared.u64 t, %1; cvt.u32.u64 %0, t; }" : "=r"(r) : "l"(p));
    return r;
}
__device__ __forceinline__ ull shflx64(ull v, int m) {
    return __shfl_xor_sync(0xffffffffu, v, m);
}
__device__ __forceinline__ float sigf(float x)   { return __fdividef(1.f, 1.f + __expf(-x)); }
__device__ __forceinline__ float tanhf2(float x) { return __fdividef(2.f, 1.f + __expf(-2.f * x)) - 1.f; }

// ---------- prep: quad-pack transposed weights ----------
__global__ void decoder_prep(const float* __restrict__ Wih, const float* __restrict__ Whh) {
    int i = blockIdx.x * blockDim.x + threadIdx.x;   // i = k*128 + u
    if (i < Hq * Hq) {
        int u = i & 127, k = i >> 7;
        float4 wh, wc;
        wh.x = Whh[u * Hq + k];          wc.x = Wih[u * Hq + k]          + wh.x;
        wh.y = Whh[(u + 128) * Hq + k];  wc.y = Wih[(u + 128) * Hq + k]  + wh.y;
        wh.z = Whh[(u + 256) * Hq + k];  wc.z = Wih[(u + 256) * Hq + k]  + wh.z;
        wh.w = Whh[(u + 384) * Hq + k];  wc.w = Wih[(u + 384) * Hq + k]  + wh.w;
        g_Wq[i] = wc;  g_Whq[i] = wh;
    }
}

// ---------- fused GEMM: 8 gate rows + 1 out row over 32 k's, P batch-pairs ----------
// T0: step 0 -> quad0 via LDG from g_Whq (w0g); else quad0 via SMEM (w0s).
template <int P, bool T0>
__device__ __forceinline__ void gemm32(
    const float4* __restrict__ w0s,   // SMEM Wq_s + kg*32*64 + u0 (stride 64)
    const float4* __restrict__ w0g,   // g_Whq + kg*32*128 + u0    (stride 128)
    const float4* __restrict__ w1g,   // (T0? g_Whq : g_Wq) + kg*32*128 + u1
    const float*  __restrict__ wo_sp, // SMEM Wo_s + kg*32*64 + u0
    unsigned hbk,                     // h_s byte addr + kg*32*80 (+32 if bph1)
    ull (&A)[2][4][4], ull (&Aw)[4])
{
#pragma unroll 4
    for (int i = 0; i < 32; i++) {
        float4 w0 = T0 ? __ldg(w0g + i * 128) : w0s[i * 64];
        float4 w1 = __ldg(w1g + i * 128);
        float  wo = wo_sp[i * 64];
        unsigned a = hbk + (unsigned)(i * (HS * 4));
        ull hh[4];
        if (P == 4) {
            ldsv2(hh[0], hh[1], a);        // slots 0..3
            ldsv2(hh[2], hh[3], a + 16);   // slots 4..7
        } else {
            ldsv2(hh[0], hh[1], a);        // slots 8..11 (hbk pre-offset +32)
            hh[2] = lds64(a + 16);         // slots 12,13
        }
        ull wi0 = dup2(w0.x), wf0 = dup2(w0.y), wg0 = dup2(w0.z), wo0 = dup2(w0.w);
        ull wi1 = dup2(w1.x), wf1 = dup2(w1.y), wg1 = dup2(w1.z), wo1 = dup2(w1.w);
        ull wwo = dup2(wo);
#pragma unroll
        for (int bp = 0; bp < P; bp++) {
            A[0][0][bp] = fma2(wi0, hh[bp], A[0][0][bp]);
            A[0][1][bp] = fma2(wf0, hh[bp], A[0][1][bp]);
            A[0][2][bp] = fma2(wg0, hh[bp], A[0][2][bp]);
            A[0][3][bp] = fma2(wo0, hh[bp], A[0][3][bp]);
            A[1][0][bp] = fma2(wi1, hh[bp], A[1][0][bp]);
            A[1][1][bp] = fma2(wf1, hh[bp], A[1][1][bp]);
            A[1][2][bp] = fma2(wg1, hh[bp], A[1][2][bp]);
            A[1][3][bp] = fma2(wo1, hh[bp], A[1][3][bp]);
            Aw[bp]      = fma2(wwo, hh[bp], Aw[bp]);
        }
    }
}

// SMEM layout (float offsets):
//   Wq_s [128k][64u] f4 @ 0      (32768)  quad weights, units 0..63
//   Wo_s [128k][64o]    @ 32768  ( 8192)  Wo transposed
//   h_s  [128][20]      @ 40960  ( 2560)  h transposed [k][slot]
//   ob   [64o][15]      @ 43520  (  960)  out staging
#define OFF_WOS 32768
#define OFF_H   40960
#define OFF_OB  43520
#define SMEM_FLOATS 44480
#define SMEM_BYTES  (SMEM_FLOATS * 4)

__global__ void __launch_bounds__(512, 1) decoder_main(
    const float* __restrict__ latent, const float* __restrict__ fc_w, const float* __restrict__ fc_b,
    const float* __restrict__ b_ih,   const float* __restrict__ b_hh,
    const float* __restrict__ Wo,     const float* __restrict__ bo,
    float* __restrict__ out)
{
    extern __shared__ float sm[];
    float4* Wq_s = reinterpret_cast<float4*>(sm);
    float* Wo_s = sm + OFF_WOS;
    float* h_s  = sm + OFF_H;
    float* ob   = sm + OFF_OB;

    const int tid  = threadIdx.x;
    const int lane = tid & 31;
    const int warp = tid >> 5;                 // 0..15
    const int kg   = lane >> 3;                // k-group 0..3
    const int kgb0 = kg & 1;
    const int kgb1 = kg >> 1;
    const int u0   = (warp & 7) * 8 + (lane & 7);  // 0..63
    const int u1   = u0 + 64;
    const int bph  = warp >> 3;                // 0: bp0-3, 1: bp4-6
    const int cta  = blockIdx.x;
    int bstart, nb;
    if (cta < 124) { bstart = cta * 14;                nb = 14; }
    else           { bstart = 1736 + (cta - 124) * 13; nb = 13; }

    // Stage quad-0 weights (units 0..63) and Wo into SMEM.
    for (int i = tid; i < Hq * 64; i += 512) {
        int k = i >> 6, u = i & 63;
        Wq_s[i] = g_Wq[k * Hq + u];
    }
    for (int i = tid; i < Hq * Oq; i += 512) {
        int k = i >> 6, o = i & 63;
        Wo_s[i] = Wo[o * Hq + k];
    }
    for (int i = tid; i < Hq * HS; i += 512) h_s[i] = 0.f;
    __syncthreads();

    // h0 = latent @ fc_w^T + fc_b  (pad slots stay 0)
    for (int i = tid; i < 14 * Hq; i += 512) {
        int slot = i >> 7, hk = i & 127;
        float acc = 0.f;
        if (slot < nb) {
            acc = fc_b[hk];
            const float* lp = latent + (size_t)(bstart + slot) * Lq;
            const float* wp = fc_w + hk * Lq;
#pragma unroll 8
            for (int l = 0; l < Lq; l++) acc += lp[l] * wp[l];
        }
        h_s[hk * HS + slot] = acc;
    }

    // Biases: only kg==0 lanes inject them (summed once across the xor-tree).
    ull bb[2][4];
#pragma unroll
    for (int us = 0; us < 2; us++) {
        int u = us ? u1 : u0;
#pragma unroll
        for (int g = 0; g < 4; g++) {
            float v = b_ih[g * 128 + u] + b_hh[g * 128 + u];
            bb[us][g] = (kg == 0) ? dup2(v) : 0ull;
        }
    }
    const ull bow = (kg == 0) ? dup2(bo[u0]) : 0ull;

    const int P = bph ? 3 : 4;
    // Register-resident cell state. Post-reduction ownership:
    //   unit = kgb1 ? u1 : u0;  bp = bph*4 + (bph0: kgb0*2+j, j=0,1)
    //                               (bph1: kgb0==0 -> 4+j (j=0,1); kgb0==1 -> 6)
    ull cR[2] = {0ull, 0ull};
    const int U = kgb1 ? u1 : u0;

    const unsigned hb  = sm_u32(h_s);
    const unsigned obb = sm_u32(ob);
    const unsigned hbk = hb + (unsigned)(kg * 32 * (HS * 4) + bph * 32);
    const float4* w0s = Wq_s  + kg * 32 * 64 + u0;
    const float4* w0g = g_Whq + kg * 32 * Hq + u0;
    const float4* wh1 = g_Whq + kg * 32 * Hq + u1;
    const float4* wc1 = g_Wq  + kg * 32 * Hq + u1;
    const float*  wo_sp = Wo_s + kg * 32 * Oq + u0;
    __syncthreads();

    for (int t = 0; t < Tq; t++) {
        // ---- phase 1: fused gate+out GEMM over this lane's 32 k's ----
        ull A[2][4][4], Aw[4];
#pragma unroll
        for (int us = 0; us < 2; us++)
#pragma unroll
            for (int g = 0; g < 4; g++)
#pragma unroll
                for (int bp = 0; bp < 4; bp++) A[us][g][bp] = bb[us][g];
#pragma unroll
        for (int j = 0; j < 4; j++) Aw[j] = bow;

        if (bph == 0) {
            if (t == 0) gemm32<4, true >(w0s, w0g, wh1, wo_sp, hbk, A, Aw);
            else        gemm32<4, false>(w0s, w0g, wc1, wo_sp, hbk, A, Aw);
        } else {
            if (t == 0) gemm32<3, true >(w0s, w0g, wh1, wo_sp, hbk, A, Aw);
            else        gemm32<3, false>(w0s, w0g, wc1, wo_sp, hbk, A, Aw);
        }

        // ---- kg reduce-scatter ----
        // Stage A (xor 16): kgb1=0 keeps quad0's P accums, kgb1=1 keeps quad1's.
        ull K[4][4];
#pragma unroll
        for (int g = 0; g < 4; g++)
#pragma unroll
            for (int bp = 0; bp < 4; bp++) {
                ull snd  = kgb1 ? A[0][g][bp] : A[1][g][bp];
                ull rcv  = shflx64(snd, 16);
                ull mine = kgb1 ? A[1][g][bp] : A[0][g][bp];
                K[g][bp] = add2(mine, rcv);
            }
        // Stage B (xor 8): split bp. bph0: kgb0=0 keeps idx{0,1}, kgb0=1 idx{2,3}.
        //                  bph1: kgb0=0 keeps idx{0,1}, kgb0=1 idx{2}.
#pragma unroll
        for (int g = 0; g < 4; g++)
#pragma unroll
            for (int j = 0; j < 2; j++) {
                ull snd;
                if (bph == 0) snd = kgb0 ? K[g][j] : K[g][2 + j];
                else          snd = kgb0 ? K[g][j] : ((j == 0) ? K[g][2] : K[g][0]);
                ull rcv = shflx64(snd, 8);
                if (bph == 0) {
                    if (!kgb0) K[g][j]     = add2(K[g][j],     rcv);
                    else       K[g][2 + j] = add2(K[g][2 + j], rcv);
                } else {
                    if (!kgb0)       K[g][j] = add2(K[g][j], rcv);
                    else if (j == 0) K[g][2] = add2(K[g][2], rcv);
                }
            }
        // Out-row full butterfly over kg.
#pragma unroll
        for (int j = 0; j < 4; j++) Aw[j] = add2(Aw[j], shflx64(Aw[j], 16));
#pragma unroll
        for (int j = 0; j < 4; j++) Aw[j] = add2(Aw[j], shflx64(Aw[j], 8));

        __syncthreads();   // all h_s reads of this step done

        // ---- phase 2: elementwise cell update in registers; write h to SMEM ----
#pragma unroll
        for (int j = 0; j < 2; j++) {
            bool active = (bph == 0) || (!kgb0) || (j == 0);
            if (active) {
                int idx = (bph == 0) ? (kgb0 * 2 + j) : (kgb0 ? 2 : j);
                int bp  = (bph == 0) ? idx : (kgb0 ? 6 : 4 + j);
                float gi0, gi1, gf0, gf1, gg0, gg1, go0, go1, cc0, cc1;
                unpk(K[0][idx], gi0, gi1);
                unpk(K[1][idx], gf0, gf1);
                unpk(K[2][idx], gg0, gg1);
                unpk(K[3][idx], go0, go1);
                unpk(cR[j], cc0, cc1);
                float nc0 = sigf(gf0) * cc0 + sigf(gi0) * tanhf2(gg0);
                float nc1 = sigf(gf1) * cc1 + sigf(gi1) * tanhf2(gg1);
                float hv0 = sigf(go0) * tanhf2(nc0);
                float hv1 = sigf(go1) * tanhf2(nc1);
                cR[j] = pack2(nc0, nc1);
                sts64(hb + (unsigned)(U * (HS * 4) + bp * 8), pack2(hv0, hv1));
            }
        }

        // ---- stage out[t-1]: kg==0 lanes write full sums ----
        if (kg == 0) {
            unsigned ow = obb + (unsigned)(u0 * 60);   // 15 floats/row
#pragma unroll
            for (int j = 0; j < 4; j++) {
                if (j < P) {
                    int s0 = bph * 8 + 2 * j;
                    float lo, hi;
                    unpk(Aw[j], lo, hi);
                    sts32(ow + (unsigned)(s0 * 4),     lo);
                    sts32(ow + (unsigned)(s0 * 4 + 4), hi);
                }
            }
        }
        __syncthreads();

        // ---- coalesced store of out[t-1]: warps 0-6 -> slots 2w, 2w+1 ----
        if (t > 0 && warp < 7) {
#pragma unroll
            for (int si = 0; si < 2; si++) {
                int s = 2 * warp + si;
                if (s < nb) {
                    float v0 = ob[lane * 15 + s];
                    float v1 = ob[(lane + 32) * 15 + s];
                    size_t base = ((size_t)(bstart + s) * Tq + (t - 1)) * Oq;
                    out[base + lane]      = v0;
                    out[base + lane + 32] = v1;
                }
            }
        }
    }

    // ---- tail: out[T-1] from final h ----
    {
        ull Aw[4];
#pragma unroll
        for (int j = 0; j < 4; j++) Aw[j] = bow;
#pragma unroll 4
        for (int i = 0; i < 32; i++) {
            float wo = wo_sp[i * 64];
            ull wwo = dup2(wo);
            unsigned a = hbk + (unsigned)(i * (HS * 4));
            ull hh[4];
            if (bph == 0) { ldsv2(hh[0], hh[1], a); ldsv2(hh[2], hh[3], a + 16); }
            else          { ldsv2(hh[0], hh[1], a); hh[2] = lds64(a + 16); hh[3] = 0ull; }
#pragma unroll
            for (int j = 0; j < 4; j++)
                if (j < P) Aw[j] = fma2(wwo, hh[j], Aw[j]);
        }
#pragma unroll
        for (int j = 0; j < 4; j++) Aw[j] = add2(Aw[j], shflx64(Aw[j], 16));
#pragma unroll
        for (int j = 0; j < 4; j++) Aw[j] = add2(Aw[j], shflx64(Aw[j], 8));

        __syncthreads();   // out[T-2] readers done with ob before overwrite

        if (kg == 0) {
            unsigned ow = obb + (unsigned)(u0 * 60);
#pragma unroll
            for (int j = 0; j < 4; j++) {
                if (j < P) {
                    int s0 = bph * 8 + 2 * j;
                    float lo, hi;
                    unpk(Aw[j], lo, hi);
                    sts32(ow + (unsigned)(s0 * 4),     lo);
                    sts32(ow + (unsigned)(s0 * 4 + 4), hi);
                }
            }
        }
        __syncthreads();
        if (warp < 7) {
#pragma unroll
            for (int si = 0; si < 2; si++) {
                int s = 2 * warp + si;
                if (s < nb) {
                    float v0 = ob[lane * 15 + s];
                    float v1 = ob[(lane + 32) * 15 + s];
                    size_t base = ((size_t)(bstart + s) * Tq + (Tq - 1)) * Oq;
                    out[base + lane]      = v0;
                    out[base + lane + 32] = v1;
                }
            }
        }
    }
}

extern "C" void kernel_launch(void* const* d_in, const int* in_sizes, int n_in,
                              void* d_out, int out_size) {
    const float* latent = (const float*)d_in[0];
    const float* fc_w   = (const float*)d_in[1];
    const float* fc_b   = (const float*)d_in[2];
    const float* W_ih   = (const float*)d_in[3];
    const float* W_hh   = (const float*)d_in[4];
    const float* b_ih   = (const float*)d_in[5];
    const float* b_hh   = (const float*)d_in[6];
    const float* Wo     = (const float*)d_in[7];
    const float* bo     = (const float*)d_in[8];
    float* out = (float*)d_out;

    cudaFuncSetAttribute(decoder_main,
                         cudaFuncAttributeMaxDynamicSharedMemorySize, SMEM_BYTES);

    decoder_prep<<<(Hq * Hq + 511) / 512, 512>>>(W_ih, W_hh);
    decoder_main<<<148, 512, SMEM_BYTES>>>(latent, fc_w, fc_b, b_ih, b_hh, Wo, bo, out);
}